// round 9
// baseline (speedup 1.0000x reference)
#include <cuda_runtime.h>
#include <cuda_bf16.h>
#include <cstdint>

#define N_BANDS    128
#define RESO       64
#define N_FRAMES   128
#define N_SAMPLES  32768
#define BATCH      16
#define N_ROWS     (BATCH * N_BANDS)

typedef unsigned long long u64;

// Pair table: g_framep[i*2048 + c*16 + b] = (frames[b,c,i], frames[b,c,min(i+1,127)])
__device__ __align__(16) float2 g_framep[N_FRAMES * N_ROWS];

__device__ __forceinline__ u64 fma2(u64 a, u64 b, u64 c) {
    u64 d;
    asm("fma.rn.f32x2 %0, %1, %2, %3;" : "=l"(d) : "l"(a), "l"(b), "l"(c));
    return d;
}
__device__ __forceinline__ u64 add2(u64 a, u64 b) {
    u64 d;
    asm("add.rn.f32x2 %0, %1, %2;" : "=l"(d) : "l"(a), "l"(b));
    return d;
}
__device__ __forceinline__ u64 dup32(float x) {
    u64 r;
    unsigned int xi = __float_as_uint(x);
    asm("mov.b64 %0, {%1, %1};" : "=l"(r) : "r"(xi));
    return r;
}
__device__ __forceinline__ float u64lo(u64 v) {
    return __uint_as_float((unsigned int)(v & 0xFFFFFFFFull));
}
__device__ __forceinline__ float u64hi(u64 v) {
    return __uint_as_float((unsigned int)(v >> 32));
}

// ---------------------------------------------------------------------------
// Kernel 1: 128 blocks (block = band index c) x 256 threads.
// softmax + matmul (f32x2 over r-pairs), writes (f_i, f_{i+1}) pairs coalesced.
// ---------------------------------------------------------------------------
__global__ __launch_bounds__(256)
void frames_kernel(const float* __restrict__ x,
                   const float* __restrict__ reso) {
    __shared__ float resT[N_FRAMES * 66];   // [f][r] padded stride 66
    __shared__ float pool2[2080];           // xs | ps; fr aliases after sync

    float* xs = pool2;                 // [b*64 + r]
    float* ps = pool2 + 1024;          // [b*66 + r]
    float* fr = pool2;                 // [f*16 + b]

    const int tid = threadIdx.x;
    const int c = blockIdx.x;

    for (int idx = tid; idx < RESO * N_FRAMES; idx += 256) {
        const int r = idx >> 7;
        const int f = idx & 127;
        resT[f * 66 + r] = reso[idx];
    }
    for (int idx = tid; idx < 16 * RESO; idx += 256) {
        const int b = idx >> 6;
        const int r = idx & 63;
        xs[idx] = x[(b * 128 + c) * RESO + r];
    }
    __syncthreads();

    {
        const int w = tid >> 5;
        const int lane = tid & 31;
        #pragma unroll
        for (int rr = 0; rr < 2; ++rr) {
            const int row = w * 2 + rr;
            float v0 = xs[row * 64 + lane];
            float v1 = xs[row * 64 + lane + 32];
            float m = fmaxf(v0, v1);
            #pragma unroll
            for (int off = 16; off > 0; off >>= 1)
                m = fmaxf(m, __shfl_xor_sync(0xFFFFFFFFu, m, off));
            float e0 = __expf(v0 - m);
            float e1 = __expf(v1 - m);
            float s = e0 + e1;
            #pragma unroll
            for (int off = 16; off > 0; off >>= 1)
                s += __shfl_xor_sync(0xFFFFFFFFu, s, off);
            float inv = 1.0f / s;
            ps[row * 66 + lane]      = e0 * inv;
            ps[row * 66 + lane + 32] = e1 * inv;
        }
    }
    __syncthreads();

    float v[8];
    {
        const int b  = tid & 15;
        const int f0 = tid >> 4;
        u64 acc2[8];
        #pragma unroll
        for (int i = 0; i < 8; ++i) acc2[i] = 0ull;

        #pragma unroll 4
        for (int rr = 0; rr < RESO / 2; ++rr) {
            const u64 psp =
                *reinterpret_cast<const u64*>(&ps[b * 66 + 2 * rr]);
            #pragma unroll
            for (int i = 0; i < 8; ++i) {
                const u64 rp = *reinterpret_cast<const u64*>(
                    &resT[(f0 + 16 * i) * 66 + 2 * rr]);
                acc2[i] = fma2(rp, psp, acc2[i]);
            }
        }
        #pragma unroll
        for (int i = 0; i < 8; ++i) v[i] = u64lo(acc2[i]) + u64hi(acc2[i]);
    }
    __syncthreads();

    {
        const int b  = tid & 15;
        const int f0 = tid >> 4;
        #pragma unroll
        for (int i = 0; i < 8; ++i)
            fr[(f0 + 16 * i) * 16 + b] = v[i];
    }
    __syncthreads();

    {
        const int b  = tid & 15;
        const int f0 = tid >> 4;
        #pragma unroll
        for (int k = 0; k < 8; ++k) {
            const int p = f0 + 16 * k;
            const int pn = (p + 1 < N_FRAMES) ? p + 1 : N_FRAMES - 1;
            const float lo = fr[p * 16 + b];
            const float hi = fr[pn * 16 + b];
            g_framep[p * N_ROWS + c * 16 + b] = make_float2(lo, hi);
        }
    }
}

// ---------------------------------------------------------------------------
// Kernel 2: 1024 blocks x 256 threads, 6 blocks/SM. Block n = samples
// [32n, 32n+32); frame pair uniform: i0 = (n<4) ? 0 : (n-4)>>3
// (crossings at s = 383.5 + 256k are 32-aligned).
// smem 24KB: FP pair table (16KB) + fb ring 2 x 4KB (32-band chunks).
// Thread: sg = tid&7 (4 samples), bq = (tid>>3)&7 (2 batches),
// bs = tid>>6 (8-band quarter of each chunk). 8 u64 accs, lanes=(dot0,dot1).
// Per band: 1 LDS.128 fb + 4 dup MOV + 1 LDS.128 FP + 8 fma2.
// Epilogue: 4-way bs reduce via smem (reuses FP region), local interp, STG.128.
// ---------------------------------------------------------------------------
__global__ __launch_bounds__(256, 6)
void mix_kernel(const float* __restrict__ fb,
                float* __restrict__ out) {
    __shared__ __align__(16) float fbbuf[2 * 1024];   // 8 KB ring
    __shared__ __align__(16) u64 FPs[N_ROWS];         // 16 KB pair table

    const int tid = threadIdx.x;
    const int n = blockIdx.x;
    const int s_base = n * 32;

    const int i0 = (n < 4) ? 0 : ((n - 4) >> 3);

    const unsigned int fb_s0 = (unsigned int)__cvta_generic_to_shared(&fbbuf[0]);
    const unsigned int FP_s0 = (unsigned int)__cvta_generic_to_shared(&FPs[0]);

    // fb chunk = 32 bands x 32 samples = 4KB; 1 x 16B per thread. 128B/band.
#define STAGE_FB(CHUNK, BUF)                                                  \
    {                                                                         \
        const int o = tid * 16;                                               \
        const int band = o >> 7;                                              \
        const int within = o & 127;                                           \
        const float* g = fb + ((CHUNK) * 32 + band) * N_SAMPLES               \
                           + s_base + (within >> 2);                          \
        asm volatile("cp.async.cg.shared.global [%0], [%1], 16;\n"            \
                     :: "r"(fb_s0 + (BUF) * 4096 + o), "l"(g));               \
        asm volatile("cp.async.commit_group;\n");                             \
    }

    // Group 0: FP pair table (16KB) + fb chunk 0.  Group 1: chunk 1.
    {
        const char* gp = (const char*)(g_framep + i0 * N_ROWS);
        #pragma unroll
        for (int i = 0; i < 4; ++i) {
            const int o = (i * 256 + tid) * 16;
            asm volatile("cp.async.cg.shared.global [%0], [%1], 16;\n"
                         :: "r"(FP_s0 + o), "l"(gp + o));
        }
        {
            const int o = tid * 16;
            const int band = o >> 7;
            const int within = o & 127;
            const float* g = fb + band * N_SAMPLES + s_base + (within >> 2);
            asm volatile("cp.async.cg.shared.global [%0], [%1], 16;\n"
                         :: "r"(fb_s0 + o), "l"(g));
        }
        asm volatile("cp.async.commit_group;\n");
    }
    STAGE_FB(1, 1);

    const int sg = tid & 7;              // 4-sample group (of 32)
    const int bq = (tid >> 3) & 7;       // batch pair (batches 2bq, 2bq+1)
    const int bs = tid >> 6;             // 8-band quarter within chunk

    u64 acc[8];   // acc[bp*4+j]: batch 2bq+bp, sample j; lanes (dot0, dot1)
    #pragma unroll
    for (int p = 0; p < 8; ++p) acc[p] = 0ull;

#define PROC(BUF, CH)                                                         \
    {                                                                         \
        _Pragma("unroll")                                                     \
        for (int cl = 0; cl < 8; ++cl) {                                      \
            const int cb = bs * 8 + cl;                                       \
            const int c  = (CH) * 32 + cb;                                    \
            const float4 fv = *reinterpret_cast<const float4*>(               \
                &fbbuf[(BUF) * 1024 + cb * 32 + sg * 4]);                     \
            const u64 d0 = dup32(fv.x);                                       \
            const u64 d1 = dup32(fv.y);                                       \
            const u64 d2 = dup32(fv.z);                                       \
            const u64 d3 = dup32(fv.w);                                       \
            const ulonglong2 fp2 = *reinterpret_cast<const ulonglong2*>(      \
                &FPs[c * 16 + bq * 2]);                                       \
            acc[0] = fma2(fp2.x, d0, acc[0]);                                 \
            acc[1] = fma2(fp2.x, d1, acc[1]);                                 \
            acc[2] = fma2(fp2.x, d2, acc[2]);                                 \
            acc[3] = fma2(fp2.x, d3, acc[3]);                                 \
            acc[4] = fma2(fp2.y, d0, acc[4]);                                 \
            acc[5] = fma2(fp2.y, d1, acc[5]);                                 \
            acc[6] = fma2(fp2.y, d2, acc[6]);                                 \
            acc[7] = fma2(fp2.y, d3, acc[7]);                                 \
        }                                                                     \
    }

#define WAITG(N) asm volatile("cp.async.wait_group %0;\n" :: "n"(N) : "memory")

    WAITG(1); __syncthreads(); PROC(0, 0);
    __syncthreads(); STAGE_FB(2, 0);
    WAITG(1); __syncthreads(); PROC(1, 1);
    __syncthreads(); STAGE_FB(3, 1);
    WAITG(1); __syncthreads(); PROC(0, 2);
    WAITG(0); __syncthreads(); PROC(1, 3);

#undef STAGE_FB
#undef PROC
#undef WAITG

    // --- Epilogue: 4-way reduce over bs (scratch reuses FP region) ---
    __syncthreads();   // all reads of FPs/fbbuf done
    u64* S = reinterpret_cast<u64*>(&FPs[0]);   // 2048 u64 capacity
    if (bs > 0) {
        const int e = tid & 63;
        #pragma unroll
        for (int p = 0; p < 8; ++p)
            S[(bs - 1) * 640 + e * 9 + p] = acc[p];   // padded stride 9
    }
    __syncthreads();
    if (tid < 64) {
        const int s0 = s_base + sg * 4;
        float w[4];
        #pragma unroll
        for (int j = 0; j < 4; ++j) {
            float pos = (float)(s0 + j) * (1.0f / 256.0f)
                        + (0.5f / 256.0f - 0.5f);
            pos = fminf(fmaxf(pos, 0.0f), 127.0f);
            w[j] = pos - floorf(pos);
        }
        #pragma unroll
        for (int bp = 0; bp < 2; ++bp) {
            float4 o;
            float* ov = &o.x;
            #pragma unroll
            for (int j = 0; j < 4; ++j) {
                u64 A = acc[bp * 4 + j];
                A = add2(A, S[0 * 640 + tid * 9 + bp * 4 + j]);
                A = add2(A, S[1 * 640 + tid * 9 + bp * 4 + j]);
                A = add2(A, S[2 * 640 + tid * 9 + bp * 4 + j]);
                const float a0 = u64lo(A);
                const float a1 = u64hi(A);
                ov[j] = fmaf(w[j], a1 - a0, a0) * (1.0f / 128.0f);
            }
            *reinterpret_cast<float4*>(
                out + (bq * 2 + bp) * N_SAMPLES + s0) = o;
        }
    }
}

// ---------------------------------------------------------------------------
extern "C" void kernel_launch(void* const* d_in, const int* in_sizes, int n_in,
                              void* d_out, int out_size) {
    const float* x = nullptr;      // (16,128,64)    = 131072
    const float* reso = nullptr;   // (64,128)       = 8192
    const float* fb = nullptr;     // (1,128,32768)  = 4194304
    for (int i = 0; i < n_in; ++i) {
        if (in_sizes[i] == BATCH * N_BANDS * RESO)      x = (const float*)d_in[i];
        else if (in_sizes[i] == RESO * N_FRAMES)        reso = (const float*)d_in[i];
        else if (in_sizes[i] == N_BANDS * N_SAMPLES)    fb = (const float*)d_in[i];
    }
    float* out = (float*)d_out;

    frames_kernel<<<N_BANDS, 256>>>(x, reso);
    mix_kernel<<<N_SAMPLES / 32, 256>>>(fb, out);
}